// round 11
// baseline (speedup 1.0000x reference)
#include <cuda_runtime.h>
#include <cuda_bf16.h>
#include <mma.h>
#include <math.h>

using namespace nvcuda;

#define NN 100000
#define EE 400000

typedef unsigned long long u64;
typedef unsigned int u32;

// ---- scratch (device globals: allocation-free) ----
__device__ float g_upd[NN * 128];
__device__ float g_Us[NN * 256];        // per-node src tables: [U1s | Ugs]
__device__ float g_Ud[NN * 256];        // per-node dst tables: [U1d | Ugd]
__device__ float g_As[128 * 128];       // W_src@W1a
__device__ float g_Gs[128 * 128];       // W_src@Wg1a
__device__ float g_Ad[128 * 128];       // W_dst@W1b
__device__ float g_Gd[128 * 128];       // W_dst@Wg1b
__device__ float g_fb[4][128];          // folded biases
// pre-split bf16 weights, [k][n] row-major with ld=136 (ldmatrix-friendly):
// index: 0=As 1=Gs 2=Ad 3=Gd 4=W2 5=W3
__device__ unsigned short g_sWhi[6][128 * 136];
__device__ unsigned short g_sWlo[6][128 * 136];

// ---- smem layout (bytes) ----
#define LDA   136            // bf16 elements per row (272 B)
#define TILE_B (128 * LDA * 2)   // 34816
#define A_HI   0
#define A_LO   34816
#define B_HI0  69632
#define B_LO0  104448
#define B_HI1  139264
#define B_LO1  174080
#define STAGE  208896        // 8 warps x 16x20 f32 = 10240
#define STG_LD 20
#define STG_WARP 1280
#define EOFF_B2   219136
#define EOFF_B3   219648
#define EOFF_LNG  220160
#define EOFF_LNB  220672
#define EOFF_GATE 221184
#define EOFF_DST  221696
#define EDGE_SMEM 222208
#define NOFF_FB0  219136
#define NOFF_FB1  219648
#define NODE_SMEM 220160

// =============================== helpers ===============================
__device__ __forceinline__ float4 ld4(const float* p) { return *reinterpret_cast<const float4*>(p); }
__device__ __forceinline__ void   st4(float* p, float4 v) { *reinterpret_cast<float4*>(p) = v; }
__device__ __forceinline__ ulonglong2 ld2u64(const float* p) {
    return *reinterpret_cast<const ulonglong2*>(p);
}
__device__ __forceinline__ u64 bcast2(float a) {
    u64 r; asm("mov.b64 %0, {%1, %1};" : "=l"(r) : "f"(a)); return r;
}
__device__ __forceinline__ void ffma2(u64& d, u64 a, u64 b) {
    asm("fma.rn.f32x2 %0, %1, %2, %0;" : "+l"(d) : "l"(a), "l"(b));
}
__device__ __forceinline__ float2 unpk(u64 v) {
    float2 f; asm("mov.b64 {%0, %1}, %2;" : "=f"(f.x), "=f"(f.y) : "l"(v)); return f;
}
__device__ __forceinline__ float gelu_exact(float x) {
    return 0.5f * x * (1.0f + erff(x * 0.70710678118654752440f));
}
__device__ __forceinline__ u32 pk2(float a, float b) {
    __nv_bfloat162 t = __floats2bfloat162_rn(a, b);
    return *reinterpret_cast<u32*>(&t);
}
__device__ __forceinline__ void spl(float x, float& hi, float& lo) {
    __nv_bfloat16 h = __float2bfloat16_rn(x);
    hi = __bfloat162float(h);
    lo = x - hi;
}
// split 4 values, store 8B hi + 8B lo at [row][k0..k0+3] (ld=LDA)
__device__ __forceinline__ void split_store4(char* sm, int row, int k0,
                                             float x0, float x1, float x2, float x3) {
    float h0, l0, h1, l1, h2, l2, h3, l3;
    spl(x0, h0, l0); spl(x1, h1, l1); spl(x2, h2, l2); spl(x3, h3, l3);
    u32 o = (u32)(row * (LDA * 2) + k0 * 2);
    *reinterpret_cast<uint2*>(sm + A_HI + o) = make_uint2(pk2(h0, h1), pk2(h2, h3));
    *reinterpret_cast<uint2*>(sm + A_LO + o) = make_uint2(pk2(l0, l1), pk2(l2, l3));
}

typedef wmma::fragment<wmma::matrix_a, 16, 16, 16, __nv_bfloat16, wmma::row_major> FragA;
typedef wmma::fragment<wmma::matrix_b, 16, 16, 16, __nv_bfloat16, wmma::row_major> FragB;
typedef wmma::fragment<wmma::accumulator, 16, 16, 16, float> FragC;

// one warp: C[16,128] = A[m0:m0+16, 0:128] @ B[128,128], 3xbf16 split, fp32 acc
__device__ __forceinline__ void warp_gemm3(const char* sm, int bHi, int bLo, int m0, FragC c[8]) {
#pragma unroll
    for (int n = 0; n < 8; n++) wmma::fill_fragment(c[n], 0.0f);
    const __nv_bfloat16* aHiP = (const __nv_bfloat16*)(sm + A_HI) + m0 * LDA;
    const __nv_bfloat16* aLoP = (const __nv_bfloat16*)(sm + A_LO) + m0 * LDA;
#pragma unroll 1
    for (int prod = 0; prod < 3; prod++) {
        const __nv_bfloat16* aP = (prod == 2) ? aLoP : aHiP;
        const __nv_bfloat16* bP = (const __nv_bfloat16*)(sm + ((prod == 1) ? bLo : bHi));
#pragma unroll 1
        for (int k = 0; k < 8; k++) {
            FragA fa;
            wmma::load_matrix_sync(fa, aP + k * 16, LDA);
#pragma unroll
            for (int n = 0; n < 8; n++) {
                FragB fb;
                wmma::load_matrix_sync(fb, bP + (k * 16) * LDA + n * 16, LDA);
                wmma::mma_sync(c[n], fa, fb, c[n]);
            }
        }
    }
}

// =============================== SIMT GEMM (compose/out) ===============================
#define PFMA8(ACC, AP, BA, BB)       \
    ffma2(ACC[0], AP, BA.x);         \
    ffma2(ACC[1], AP, BA.y);         \
    ffma2(ACC[2], AP, BB.x);         \
    ffma2(ACC[3], AP, BB.y);
#define ZERO_ACC2(A)                                  \
    _Pragma("unroll") for (int _r = 0; _r < 4; _r++)  \
    _Pragma("unroll") for (int _j = 0; _j < 4; _j++) A[_r][_j] = 0ULL;
#define UNPACK8(X, ACCR)                       \
    { float2 _p;                               \
      _p = unpk(ACCR[0]); X[0] = _p.x; X[1] = _p.y; \
      _p = unpk(ACCR[1]); X[2] = _p.x; X[3] = _p.y; \
      _p = unpk(ACCR[2]); X[4] = _p.x; X[5] = _p.y; \
      _p = unpk(ACCR[3]); X[6] = _p.x; X[7] = _p.y; }

__device__ __forceinline__ void gemm64p(
    const float* __restrict__ A0, const float* __restrict__ W0g,
    float* __restrict__ sW, u64 acc[4][4], int tid)
{
    const int ty = tid >> 4, tx = tid & 15;
    const int wr = tid >> 5;
    const int wc = (tid & 31) << 2;
#pragma unroll 1
    for (int kc = 0; kc < 16; kc++) {
        __syncthreads();
        st4(sW + wr * 128 + wc, ld4(W0g + (kc * 8 + wr) * 128 + wc));
        __syncthreads();
#pragma unroll
        for (int k4 = 0; k4 < 8; k4 += 4) {
            float4 a0[4];
#pragma unroll
            for (int r = 0; r < 4; r++)
                a0[r] = ld4(A0 + (ty * 4 + r) * 128 + kc * 8 + k4);
#pragma unroll
            for (int kk = 0; kk < 4; kk++) {
                const int k = k4 + kk;
                ulonglong2 b0a = ld2u64(sW + k * 128 + tx * 4);
                ulonglong2 b0b = ld2u64(sW + k * 128 + 64 + tx * 4);
#pragma unroll
                for (int r = 0; r < 4; r++) {
                    u64 ap = bcast2((&a0[r].x)[kk]);
                    PFMA8(acc[r], ap, b0a, b0b);
                }
            }
        }
    }
}

// =============================== prep kernels ===============================
__global__ void zero_upd_kernel() {
    int i = blockIdx.x * blockDim.x + threadIdx.x;
    if (i < NN * 128 / 4) reinterpret_cast<float4*>(g_upd)[i] = make_float4(0.f, 0.f, 0.f, 0.f);
}

__global__ __launch_bounds__(256, 2) void compose_kernel(
    const float* __restrict__ Ws, const float* __restrict__ Wd,
    const float* __restrict__ W1a, const float* __restrict__ Wg1a,
    const float* __restrict__ W1b, const float* __restrict__ Wg1b)
{
    __shared__ float sA[64 * 128];
    __shared__ float sW[1024];
    const int mat = blockIdx.x >> 1, half = blockIdx.x & 1;
    const float* L = (mat < 2) ? Ws : Wd;
    const float* R = (mat == 0) ? W1a : (mat == 1) ? Wg1a : (mat == 2) ? W1b : Wg1b;
    float* O = (mat == 0) ? g_As : (mat == 1) ? g_Gs : (mat == 2) ? g_Ad : g_Gd;

    const int tid = threadIdx.x, warp = tid >> 5, lane = tid & 31;
    const int ty = tid >> 4, tx = tid & 15;
#pragma unroll
    for (int i = 0; i < 8; i++) {
        int r = warp + i * 8;
        st4(sA + r * 128 + lane * 4, ld4(L + (half * 64 + r) * 128 + lane * 4));
    }
    u64 acc[4][4];
    ZERO_ACC2(acc);
    gemm64p(sA, R, sW, acc, tid);
#pragma unroll
    for (int r = 0; r < 4; r++) {
        int row = half * 64 + ty * 4 + r;
        float x[8]; UNPACK8(x, acc[r]);
        st4(O + row * 128 + tx * 4,      make_float4(x[0], x[1], x[2], x[3]));
        st4(O + row * 128 + 64 + tx * 4, make_float4(x[4], x[5], x[6], x[7]));
    }
}

__global__ void bias_kernel(
    const float* __restrict__ bsrc, const float* __restrict__ bdst,
    const float* __restrict__ W1a, const float* __restrict__ Wg1a,
    const float* __restrict__ W1b, const float* __restrict__ Wg1b)
{
    const int mat = blockIdx.x, n = threadIdx.x;
    const float* bv = (mat < 2) ? bsrc : bdst;
    const float* R = (mat == 0) ? W1a : (mat == 1) ? Wg1a : (mat == 2) ? W1b : Wg1b;
    float s = 0.f;
    for (int j = 0; j < 128; j++) s = fmaf(bv[j], R[j * 128 + n], s);
    g_fb[mat][n] = s;
}

// split fp32 weight W[k][n] into bf16 hi/lo, [k][n] row-major with ld=LDA
__global__ void split_kernel(const float* __restrict__ W2, const float* __restrict__ W3) {
    const float* S;
    switch (blockIdx.x) {
        case 0: S = g_As; break;
        case 1: S = g_Gs; break;
        case 2: S = g_Ad; break;
        case 3: S = g_Gd; break;
        case 4: S = W2;   break;
        default: S = W3;  break;
    }
    unsigned short* H = g_sWhi[blockIdx.x];
    unsigned short* L = g_sWlo[blockIdx.x];
    for (int idx = threadIdx.x; idx < 16384; idx += blockDim.x) {
        int k = idx >> 7, n = idx & 127;
        float x = S[k * 128 + n];
        __nv_bfloat16 h = __float2bfloat16_rn(x);
        float hf = __bfloat162float(h);
        __nv_bfloat16 l = __float2bfloat16_rn(x - hf);
        H[k * LDA + n] = *reinterpret_cast<unsigned short*>(&h);
        L[k * LDA + n] = *reinterpret_cast<unsigned short*>(&l);
    }
}

// copy 4 pre-split weight tiles into smem B slots (34816 B each = 2176 uint4)
__device__ __forceinline__ void copy_b_tiles(char* sm, int m0, int m1, int tid) {
    const uint4* s0 = (const uint4*)g_sWhi[m0];
    const uint4* s1 = (const uint4*)g_sWlo[m0];
    const uint4* s2 = (const uint4*)g_sWhi[m1];
    const uint4* s3 = (const uint4*)g_sWlo[m1];
    uint4* d0 = (uint4*)(sm + B_HI0); uint4* d1 = (uint4*)(sm + B_LO0);
    uint4* d2 = (uint4*)(sm + B_HI1); uint4* d3 = (uint4*)(sm + B_LO1);
    for (int j = tid; j < 2176; j += 256) {
        d0[j] = s0[j]; d1[j] = s1[j]; d2[j] = s2[j]; d3[j] = s3[j];
    }
}

// =============================== node kernel (wmma) ===============================
// Per CTA: 128 node rows; D1 = feat@WA, D2 = feat@WG, both N=128, 3xBF16.
__global__ __launch_bounds__(256, 1) void node_kernel(const float* __restrict__ feat) {
    extern __shared__ char sm[];
    const int tid = threadIdx.x, warp = tid >> 5, lane = tid & 31;
    const int which = (blockIdx.x >= 782) ? 1 : 0;
    const size_t row0 = (size_t)(blockIdx.x - which * 782) * 128;

    // A tile: feat rows -> bf16 hi/lo
#pragma unroll 1
    for (int i = 0; i < 16; i++) {
        int r = warp * 16 + i;
        size_t gr = row0 + r;
        float4 v = make_float4(0.f, 0.f, 0.f, 0.f);
        if (gr < NN) v = ld4(feat + gr * 128 + lane * 4);
        split_store4(sm, r, lane * 4, v.x, v.y, v.z, v.w);
    }
    copy_b_tiles(sm, which * 2, which * 2 + 1, tid);
    __syncthreads();

    const int m0 = warp * 16;
    float* stage = (float*)(sm + STAGE + warp * STG_WARP);
    float* table = which ? g_Ud : g_Us;
    const int srow = lane >> 1, shalf = lane & 1;

    FragC c[8];
#pragma unroll 1
    for (int dsel = 0; dsel < 2; dsel++) {
        warp_gemm3(sm, dsel ? B_HI1 : B_HI0, dsel ? B_LO1 : B_LO0, m0, c);
        const float* fb = g_fb[which * 2 + dsel];
        size_t gr = row0 + m0 + srow;
#pragma unroll 1
        for (int n = 0; n < 8; n++) {
            wmma::store_matrix_sync(stage, c[n], STG_LD, wmma::mem_row_major);
            __syncwarp();
            if (gr < NN) {
                int cb = n * 16 + shalf * 8;
                float4 o0, o1;
                const float* sp = stage + srow * STG_LD + shalf * 8;
                o0.x = sp[0] + fb[cb + 0]; o0.y = sp[1] + fb[cb + 1];
                o0.z = sp[2] + fb[cb + 2]; o0.w = sp[3] + fb[cb + 3];
                o1.x = sp[4] + fb[cb + 4]; o1.y = sp[5] + fb[cb + 5];
                o1.z = sp[6] + fb[cb + 6]; o1.w = sp[7] + fb[cb + 7];
                st4(table + gr * 256 + dsel * 128 + cb, o0);
                st4(table + gr * 256 + dsel * 128 + cb + 4, o1);
            }
            __syncwarp();
        }
    }
}

// =============================== edge kernel (wmma) ===============================
// Per CTA: 128 edges. gather+gelu+gate -> MMA1(W2) -> gelu -> MMA2(W3) -> LN -> scatter.
__global__ __launch_bounds__(256, 1) void edge_kernel(
    const int* __restrict__ esrc, const int* __restrict__ edst,
    const float* __restrict__ b1, const float* __restrict__ b2,
    const float* __restrict__ b3,
    const float* __restrict__ lng, const float* __restrict__ lnb,
    const float* __restrict__ bg1, const float* __restrict__ Wg2,
    const float* __restrict__ bg2)
{
    extern __shared__ char sm[];
    const int tid = threadIdx.x, warp = tid >> 5, lane = tid & 31;
    const int e0 = blockIdx.x * 128;

    float* fB2  = (float*)(sm + EOFF_B2);
    float* fB3  = (float*)(sm + EOFF_B3);
    float* fLng = (float*)(sm + EOFF_LNG);
    float* fLnb = (float*)(sm + EOFF_LNB);
    float* fGate = (float*)(sm + EOFF_GATE);
    int*   iDst  = (int*)(sm + EOFF_DST);

    if (tid < 128) {
        fB2[tid] = b2[tid]; fB3[tid] = b3[tid];
        fLng[tid] = lng[tid]; fLnb[tid] = lnb[tid];
    }

    // ---- gather + h1 + gate ----
    {
        float4 b1v = ld4(b1 + lane * 4);
        float4 bgv = ld4(bg1 + lane * 4);
        float4 wgv = ld4(Wg2 + lane * 4);
#pragma unroll 1
        for (int i = 0; i < 16; i++) {
            int r = warp * 16 + i;
            int sidx = esrc[e0 + r];
            int didx = edst[e0 + r];
            const float* us = g_Us + (size_t)sidx * 256;
            const float* ud = g_Ud + (size_t)didx * 256;
            float4 a = ld4(us + lane * 4);
            float4 bq = ld4(ud + lane * 4);
            float h0 = gelu_exact(a.x + bq.x + b1v.x);
            float h1 = gelu_exact(a.y + bq.y + b1v.y);
            float h2 = gelu_exact(a.z + bq.z + b1v.z);
            float h3 = gelu_exact(a.w + bq.w + b1v.w);
            split_store4(sm, r, lane * 4, h0, h1, h2, h3);
            float4 a2 = ld4(us + 128 + lane * 4);
            float4 c2 = ld4(ud + 128 + lane * 4);
            float sg = gelu_exact(a2.x + c2.x + bgv.x) * wgv.x
                     + gelu_exact(a2.y + c2.y + bgv.y) * wgv.y
                     + gelu_exact(a2.z + c2.z + bgv.z) * wgv.z
                     + gelu_exact(a2.w + c2.w + bgv.w) * wgv.w;
#pragma unroll
            for (int off = 1; off < 32; off <<= 1)
                sg += __shfl_xor_sync(0xffffffffu, sg, off);
            if (lane == 0) { fGate[r] = sg; iDst[r] = didx; }
        }
    }
    copy_b_tiles(sm, 4, 5, tid);
    __syncthreads();

    const int m0 = warp * 16;
    float* stage = (float*)(sm + STAGE + warp * STG_WARP);
    const int srow = lane >> 1, shalf = lane & 1;
    FragC c[8];

    // ---- MMA1: D1 = h1 @ W2 ---- (A rows warp-private: no CTA sync needed below)
    warp_gemm3(sm, B_HI0, B_LO0, m0, c);

    // ---- epilogue1: h2 = gelu(D1 + b2) -> back into A tile (this warp's rows) ----
#pragma unroll 1
    for (int n = 0; n < 8; n++) {
        wmma::store_matrix_sync(stage, c[n], STG_LD, wmma::mem_row_major);
        __syncwarp();
        const float* sp = stage + srow * STG_LD + shalf * 8;
        int cb = n * 16 + shalf * 8;
        float v0 = gelu_exact(sp[0] + fB2[cb + 0]);
        float v1 = gelu_exact(sp[1] + fB2[cb + 1]);
        float v2 = gelu_exact(sp[2] + fB2[cb + 2]);
        float v3 = gelu_exact(sp[3] + fB2[cb + 3]);
        split_store4(sm, m0 + srow, cb, v0, v1, v2, v3);
        float v4 = gelu_exact(sp[4] + fB2[cb + 4]);
        float v5 = gelu_exact(sp[5] + fB2[cb + 5]);
        float v6 = gelu_exact(sp[6] + fB2[cb + 6]);
        float v7 = gelu_exact(sp[7] + fB2[cb + 7]);
        split_store4(sm, m0 + srow, cb + 4, v4, v5, v6, v7);
        __syncwarp();
    }

    // ---- MMA2: D2 = h2 @ W3 ----
    warp_gemm3(sm, B_HI1, B_LO1, m0, c);

    // ---- epilogue2: LN + gate + atomic scatter (two passes over live frags) ----
    float s = 0.f, ss = 0.f;
#pragma unroll 1
    for (int n = 0; n < 8; n++) {
        wmma::store_matrix_sync(stage, c[n], STG_LD, wmma::mem_row_major);
        __syncwarp();
        const float* sp = stage + srow * STG_LD + shalf * 8;
        int cb = n * 16 + shalf * 8;
#pragma unroll
        for (int j = 0; j < 8; j++) {
            float x = sp[j] + fB3[cb + j];
            s += x; ss += x * x;
        }
        __syncwarp();
    }
    s  += __shfl_xor_sync(0xffffffffu, s, 1);
    ss += __shfl_xor_sync(0xffffffffu, ss, 1);
    float m = s * 0.0078125f;
    float var = ss * 0.0078125f - m * m;
    float rstd = rsqrtf(var + 1e-5f);
    float gv = 1.0f / (1.0f + expf(-(fGate[m0 + srow] + bg2[0])));
    float* up = g_upd + (size_t)iDst[m0 + srow] * 128;
#pragma unroll 1
    for (int n = 0; n < 8; n++) {
        wmma::store_matrix_sync(stage, c[n], STG_LD, wmma::mem_row_major);
        __syncwarp();
        const float* sp = stage + srow * STG_LD + shalf * 8;
        int cb = n * 16 + shalf * 8;
#pragma unroll
        for (int j = 0; j < 8; j++) {
            float x = sp[j] + fB3[cb + j];
            float y = ((x - m) * rstd * fLng[cb + j] + fLnb[cb + j]) * gv;
            atomicAdd(up + cb + j, y);
        }
        __syncwarp();
    }
}

// =============================== out kernel (SIMT) ===============================
__global__ __launch_bounds__(256, 2) void out_kernel(
    const float* __restrict__ Wout, const float* __restrict__ bout,
    float* __restrict__ out)
{
    __shared__ float sU[64 * 128];
    __shared__ float sW[1024];
    const int tid = threadIdx.x, warp = tid >> 5, lane = tid & 31;
    const int ty = tid >> 4, tx = tid & 15;
    const size_t row0 = (size_t)blockIdx.x * 64;

#pragma unroll
    for (int i = 0; i < 8; i++) {
        int r = warp + i * 8;
        size_t gr = row0 + r;
        float4 v = make_float4(0.f, 0.f, 0.f, 0.f);
        if (gr < NN) v = ld4(g_upd + gr * 128 + lane * 4);
        st4(sU + r * 128 + lane * 4, v);
    }
    u64 acc[4][4];
    ZERO_ACC2(acc);
    gemm64p(sU, Wout, sW, acc, tid);

    float4 b0 = ld4(bout + tx * 4), b1v = ld4(bout + 64 + tx * 4);
#pragma unroll
    for (int r = 0; r < 4; r++) {
        size_t gr = row0 + ty * 4 + r;
        if (gr < NN) {
            float x[8]; UNPACK8(x, acc[r]);
            st4(out + gr * 128 + tx * 4,
                make_float4(x[0] + b0.x, x[1] + b0.y, x[2] + b0.z, x[3] + b0.w));
            st4(out + gr * 128 + 64 + tx * 4,
                make_float4(x[4] + b1v.x, x[5] + b1v.y, x[6] + b1v.z, x[7] + b1v.w));
        }
    }
}

extern "C" void kernel_launch(void* const* d_in, const int* in_sizes, int n_in,
                              void* d_out, int out_size)
{
    const float* feat  = (const float*)d_in[0];
    const int*   esrc  = (const int*)d_in[1];
    const int*   edst  = (const int*)d_in[2];
    const float* W_src = (const float*)d_in[3];
    const float* b_src = (const float*)d_in[4];
    const float* W_dst = (const float*)d_in[5];
    const float* b_dst = (const float*)d_in[6];
    const float* W1a   = (const float*)d_in[7];
    const float* W1b   = (const float*)d_in[8];
    const float* b1    = (const float*)d_in[9];
    const float* W2    = (const float*)d_in[10];
    const float* b2    = (const float*)d_in[11];
    const float* W3    = (const float*)d_in[12];
    const float* b3    = (const float*)d_in[13];
    const float* ln_g  = (const float*)d_in[14];
    const float* ln_b  = (const float*)d_in[15];
    const float* Wg1a  = (const float*)d_in[16];
    const float* Wg1b  = (const float*)d_in[17];
    const float* bg1   = (const float*)d_in[18];
    const float* Wg2   = (const float*)d_in[19];
    const float* bg2   = (const float*)d_in[20];
    const float* W_out = (const float*)d_in[21];
    const float* b_out = (const float*)d_in[22];
    float* out = (float*)d_out;

    cudaFuncSetAttribute(node_kernel, cudaFuncAttributeMaxDynamicSharedMemorySize, NODE_SMEM);
    cudaFuncSetAttribute(edge_kernel, cudaFuncAttributeMaxDynamicSharedMemorySize, EDGE_SMEM);

    compose_kernel<<<8, 256>>>(W_src, W_dst, W1a, Wg1a, W1b, Wg1b);
    bias_kernel<<<4, 128>>>(b_src, b_dst, W1a, Wg1a, W1b, Wg1b);
    split_kernel<<<6, 256>>>(W2, W3);
    zero_upd_kernel<<<(NN * 128 / 4 + 255) / 256, 256>>>();
    node_kernel<<<2 * 782, 256, NODE_SMEM>>>(feat);
    edge_kernel<<<EE / 128, 256, EDGE_SMEM>>>(esrc, edst, b1, b2, b3,
                                              ln_g, ln_b, bg1, Wg2, bg2);
    out_kernel<<<(NN + 63) / 64, 256>>>(W_out, b_out, out);
}

// round 13
// speedup vs baseline: 1.2665x; 1.2665x over previous
#include <cuda_runtime.h>
#include <cuda_bf16.h>
#include <mma.h>
#include <math.h>

using namespace nvcuda;

#define NN 100000
#define EE 400000

typedef unsigned long long u64;
typedef unsigned int u32;

// ---- scratch (device globals: allocation-free) ----
__device__ float g_upd[NN * 128];
__device__ float g_Us[NN * 256];        // per-node src tables: [U1s | Ugs]
__device__ float g_Ud[NN * 256];        // per-node dst tables: [U1d | Ugd]
__device__ float g_As[128 * 128];       // W_src@W1a
__device__ float g_Gs[128 * 128];       // W_src@Wg1a
__device__ float g_Ad[128 * 128];       // W_dst@W1b
__device__ float g_Gd[128 * 128];       // W_dst@Wg1b
__device__ float g_fb[4][128];          // folded biases
// pre-split bf16 weights, [k][n] row-major ld=136: 0=As 1=Gs 2=Ad 3=Gd 4=W2 5=W3
__device__ unsigned short g_sWhi[6][128 * 136];
__device__ unsigned short g_sWlo[6][128 * 136];

// ---- smem layout (bytes) ----
#define LDA   136
#define A_HI   0
#define A_LO   34816
#define B_HI0  69632
#define B_LO0  104448
#define B_HI1  139264
#define B_LO1  174080
#define STAGE  208896          // 16 warps x 16x20 f32 = 20480
#define STG_LD 20
#define STG_WB 1280
#define EOFF_GATE 229376       // 128 f32
#define EOFF_DST  229888       // 128 i32
#define EOFF_SS   230400       // [2][128] f32 partial sums
#define EOFF_SQ   231424       // [2][128] f32 partial sumsq
#define EDGE_SMEM 232448
#define NODE_SMEM 229376

// =============================== helpers ===============================
__device__ __forceinline__ float4 ld4(const float* p) { return *reinterpret_cast<const float4*>(p); }
__device__ __forceinline__ void   st4(float* p, float4 v) { *reinterpret_cast<float4*>(p) = v; }
__device__ __forceinline__ ulonglong2 ld2u64(const float* p) {
    return *reinterpret_cast<const ulonglong2*>(p);
}
__device__ __forceinline__ u64 bcast2(float a) {
    u64 r; asm("mov.b64 %0, {%1, %1};" : "=l"(r) : "f"(a)); return r;
}
__device__ __forceinline__ void ffma2(u64& d, u64 a, u64 b) {
    asm("fma.rn.f32x2 %0, %1, %2, %0;" : "+l"(d) : "l"(a), "l"(b));
}
__device__ __forceinline__ float2 unpk(u64 v) {
    float2 f; asm("mov.b64 {%0, %1}, %2;" : "=f"(f.x), "=f"(f.y) : "l"(v)); return f;
}
__device__ __forceinline__ float gelu_exact(float x) {
    return 0.5f * x * (1.0f + erff(x * 0.70710678118654752440f));
}
__device__ __forceinline__ u32 pk2(float a, float b) {
    __nv_bfloat162 t = __floats2bfloat162_rn(a, b);
    return *reinterpret_cast<u32*>(&t);
}
__device__ __forceinline__ void spl(float x, float& hi, float& lo) {
    __nv_bfloat16 h = __float2bfloat16_rn(x);
    hi = __bfloat162float(h);
    lo = x - hi;
}
__device__ __forceinline__ void split_store4(char* sm, int row, int k0,
                                             float x0, float x1, float x2, float x3) {
    float h0, l0, h1, l1, h2, l2, h3, l3;
    spl(x0, h0, l0); spl(x1, h1, l1); spl(x2, h2, l2); spl(x3, h3, l3);
    u32 o = (u32)(row * (LDA * 2) + k0 * 2);
    *reinterpret_cast<uint2*>(sm + A_HI + o) = make_uint2(pk2(h0, h1), pk2(h2, h3));
    *reinterpret_cast<uint2*>(sm + A_LO + o) = make_uint2(pk2(l0, l1), pk2(l2, l3));
}

typedef wmma::fragment<wmma::matrix_a, 16, 16, 16, __nv_bfloat16, wmma::row_major> FragA;
typedef wmma::fragment<wmma::matrix_b, 16, 16, 16, __nv_bfloat16, wmma::row_major> FragB;
typedef wmma::fragment<wmma::accumulator, 16, 16, 16, float> FragC;

// C[16, NF*16] = A[m0:m0+16, :] @ B[:, n0*16 : (n0+NF)*16], 3xbf16 split.
// B-hi fragment reused for Ahi and Alo products.
template <int NF>
__device__ __forceinline__ void warp_gemm3(const char* sm, int bHi, int bLo,
                                           int m0, int n0, FragC* c) {
#pragma unroll
    for (int j = 0; j < NF; j++) wmma::fill_fragment(c[j], 0.0f);
    const __nv_bfloat16* aHi = (const __nv_bfloat16*)(sm + A_HI) + m0 * LDA;
    const __nv_bfloat16* aLo = (const __nv_bfloat16*)(sm + A_LO) + m0 * LDA;
    const __nv_bfloat16* bH  = (const __nv_bfloat16*)(sm + bHi) + n0 * 16;
    const __nv_bfloat16* bL  = (const __nv_bfloat16*)(sm + bLo) + n0 * 16;
#pragma unroll 2
    for (int k = 0; k < 8; k++) {
        FragA fh, fl;
        wmma::load_matrix_sync(fh, aHi + k * 16, LDA);
        wmma::load_matrix_sync(fl, aLo + k * 16, LDA);
#pragma unroll
        for (int j = 0; j < NF; j++) {
            FragB fb;
            wmma::load_matrix_sync(fb, bH + (k * 16) * LDA + j * 16, LDA);
            wmma::mma_sync(c[j], fh, fb, c[j]);
            wmma::mma_sync(c[j], fl, fb, c[j]);
            wmma::load_matrix_sync(fb, bL + (k * 16) * LDA + j * 16, LDA);
            wmma::mma_sync(c[j], fh, fb, c[j]);
        }
    }
}

// =============================== SIMT GEMM (compose/out) ===============================
#define PFMA8(ACC, AP, BA, BB)       \
    ffma2(ACC[0], AP, BA.x);         \
    ffma2(ACC[1], AP, BA.y);         \
    ffma2(ACC[2], AP, BB.x);         \
    ffma2(ACC[3], AP, BB.y);
#define ZERO_ACC2(A)                                  \
    _Pragma("unroll") for (int _r = 0; _r < 4; _r++)  \
    _Pragma("unroll") for (int _j = 0; _j < 4; _j++) A[_r][_j] = 0ULL;
#define UNPACK8(X, ACCR)                       \
    { float2 _p;                               \
      _p = unpk(ACCR[0]); X[0] = _p.x; X[1] = _p.y; \
      _p = unpk(ACCR[1]); X[2] = _p.x; X[3] = _p.y; \
      _p = unpk(ACCR[2]); X[4] = _p.x; X[5] = _p.y; \
      _p = unpk(ACCR[3]); X[6] = _p.x; X[7] = _p.y; }

__device__ __forceinline__ void gemm64p(
    const float* __restrict__ A0, const float* __restrict__ W0g,
    float* __restrict__ sW, u64 acc[4][4], int tid)
{
    const int ty = tid >> 4, tx = tid & 15;
    const int wr = tid >> 5;
    const int wc = (tid & 31) << 2;
#pragma unroll 1
    for (int kc = 0; kc < 16; kc++) {
        __syncthreads();
        st4(sW + wr * 128 + wc, ld4(W0g + (kc * 8 + wr) * 128 + wc));
        __syncthreads();
#pragma unroll
        for (int k4 = 0; k4 < 8; k4 += 4) {
            float4 a0[4];
#pragma unroll
            for (int r = 0; r < 4; r++)
                a0[r] = ld4(A0 + (ty * 4 + r) * 128 + kc * 8 + k4);
#pragma unroll
            for (int kk = 0; kk < 4; kk++) {
                const int k = k4 + kk;
                ulonglong2 b0a = ld2u64(sW + k * 128 + tx * 4);
                ulonglong2 b0b = ld2u64(sW + k * 128 + 64 + tx * 4);
#pragma unroll
                for (int r = 0; r < 4; r++) {
                    u64 ap = bcast2((&a0[r].x)[kk]);
                    PFMA8(acc[r], ap, b0a, b0b);
                }
            }
        }
    }
}

// =============================== prep kernels ===============================
__global__ void zero_upd_kernel() {
    int i = blockIdx.x * blockDim.x + threadIdx.x;
    if (i < NN * 128 / 4) reinterpret_cast<float4*>(g_upd)[i] = make_float4(0.f, 0.f, 0.f, 0.f);
}

__global__ __launch_bounds__(256, 2) void compose_kernel(
    const float* __restrict__ Ws, const float* __restrict__ Wd,
    const float* __restrict__ W1a, const float* __restrict__ Wg1a,
    const float* __restrict__ W1b, const float* __restrict__ Wg1b)
{
    __shared__ float sA[64 * 128];
    __shared__ float sW[1024];
    const int mat = blockIdx.x >> 1, half = blockIdx.x & 1;
    const float* L = (mat < 2) ? Ws : Wd;
    const float* R = (mat == 0) ? W1a : (mat == 1) ? Wg1a : (mat == 2) ? W1b : Wg1b;
    float* O = (mat == 0) ? g_As : (mat == 1) ? g_Gs : (mat == 2) ? g_Ad : g_Gd;

    const int tid = threadIdx.x, warp = tid >> 5, lane = tid & 31;
    const int ty = tid >> 4, tx = tid & 15;
#pragma unroll
    for (int i = 0; i < 8; i++) {
        int r = warp + i * 8;
        st4(sA + r * 128 + lane * 4, ld4(L + (half * 64 + r) * 128 + lane * 4));
    }
    u64 acc[4][4];
    ZERO_ACC2(acc);
    gemm64p(sA, R, sW, acc, tid);
#pragma unroll
    for (int r = 0; r < 4; r++) {
        int row = half * 64 + ty * 4 + r;
        float x[8]; UNPACK8(x, acc[r]);
        st4(O + row * 128 + tx * 4,      make_float4(x[0], x[1], x[2], x[3]));
        st4(O + row * 128 + 64 + tx * 4, make_float4(x[4], x[5], x[6], x[7]));
    }
}

__global__ void bias_kernel(
    const float* __restrict__ bsrc, const float* __restrict__ bdst,
    const float* __restrict__ W1a, const float* __restrict__ Wg1a,
    const float* __restrict__ W1b, const float* __restrict__ Wg1b)
{
    const int mat = blockIdx.x, n = threadIdx.x;
    const float* bv = (mat < 2) ? bsrc : bdst;
    const float* R = (mat == 0) ? W1a : (mat == 1) ? Wg1a : (mat == 2) ? W1b : Wg1b;
    float s = 0.f;
    for (int j = 0; j < 128; j++) s = fmaf(bv[j], R[j * 128 + n], s);
    g_fb[mat][n] = s;
}

__global__ void split_kernel(const float* __restrict__ W2, const float* __restrict__ W3) {
    const float* S;
    switch (blockIdx.x) {
        case 0: S = g_As; break;
        case 1: S = g_Gs; break;
        case 2: S = g_Ad; break;
        case 3: S = g_Gd; break;
        case 4: S = W2;   break;
        default: S = W3;  break;
    }
    unsigned short* H = g_sWhi[blockIdx.x];
    unsigned short* L = g_sWlo[blockIdx.x];
    for (int idx = threadIdx.x; idx < 16384; idx += blockDim.x) {
        int k = idx >> 7, n = idx & 127;
        float x = S[k * 128 + n];
        __nv_bfloat16 h = __float2bfloat16_rn(x);
        float hf = __bfloat162float(h);
        __nv_bfloat16 l = __float2bfloat16_rn(x - hf);
        H[k * LDA + n] = *reinterpret_cast<unsigned short*>(&h);
        L[k * LDA + n] = *reinterpret_cast<unsigned short*>(&l);
    }
}

// copy 4 pre-split weight tiles into smem B slots (34816 B each = 2176 uint4)
__device__ __forceinline__ void copy_b_tiles(char* sm, int m0, int m1, int tid, int nthr) {
    const uint4* s0 = (const uint4*)g_sWhi[m0];
    const uint4* s1 = (const uint4*)g_sWlo[m0];
    const uint4* s2 = (const uint4*)g_sWhi[m1];
    const uint4* s3 = (const uint4*)g_sWlo[m1];
    uint4* d0 = (uint4*)(sm + B_HI0); uint4* d1 = (uint4*)(sm + B_LO0);
    uint4* d2 = (uint4*)(sm + B_HI1); uint4* d3 = (uint4*)(sm + B_LO1);
    for (int j = tid; j < 2176; j += nthr) {
        d0[j] = s0[j]; d1[j] = s1[j]; d2[j] = s2[j]; d3[j] = s3[j];
    }
}

// =============================== node kernel (wmma, 16 warps) ===============================
// CTA = 128 rows; warp w<8: D1 strip (w), warp w>=8: D2 strip (w-8). Each warp full N=128.
__global__ __launch_bounds__(512, 1) void node_kernel(const float* __restrict__ feat) {
    extern __shared__ char sm[];
    const int tid = threadIdx.x, warp = tid >> 5, lane = tid & 31;
    const int which = (blockIdx.x >= 782) ? 1 : 0;
    const size_t row0 = (size_t)(blockIdx.x - which * 782) * 128;

#pragma unroll 1
    for (int i = 0; i < 8; i++) {
        int r = warp * 8 + i;
        size_t gr = row0 + r;
        float4 v = make_float4(0.f, 0.f, 0.f, 0.f);
        if (gr < NN) v = ld4(feat + gr * 128 + lane * 4);
        split_store4(sm, r, lane * 4, v.x, v.y, v.z, v.w);
    }
    copy_b_tiles(sm, which * 2, which * 2 + 1, tid, 512);
    __syncthreads();

    const int wd = warp >> 3, wr = warp & 7, m0 = wr * 16;
    FragC c[8];
    warp_gemm3<8>(sm, wd ? B_HI1 : B_HI0, wd ? B_LO1 : B_LO0, m0, 0, c);

    float* stage = (float*)(sm + STAGE + warp * STG_WB);
    const float* fb = g_fb[which * 2 + wd];
    float* table = which ? g_Ud : g_Us;
    const int srow = lane >> 1, shalf = lane & 1;
    const size_t gr = row0 + m0 + srow;
#pragma unroll 1
    for (int n = 0; n < 8; n++) {
        wmma::store_matrix_sync(stage, c[n], STG_LD, wmma::mem_row_major);
        __syncwarp();
        if (gr < NN) {
            int cb = n * 16 + shalf * 8;
            const float* sp = stage + srow * STG_LD + shalf * 8;
            float4 f0 = ld4(fb + cb), f1 = ld4(fb + cb + 4);
            st4(table + gr * 256 + wd * 128 + cb,
                make_float4(sp[0] + f0.x, sp[1] + f0.y, sp[2] + f0.z, sp[3] + f0.w));
            st4(table + gr * 256 + wd * 128 + cb + 4,
                make_float4(sp[4] + f1.x, sp[5] + f1.y, sp[6] + f1.z, sp[7] + f1.w));
        }
        __syncwarp();
    }
}

// =============================== edge kernel (wmma, 16 warps, split-N) ===============================
// CTA = 128 edges. Warp w: rows strip (w&7), cols half (w>>3).
__global__ __launch_bounds__(512, 1) void edge_kernel(
    const int* __restrict__ esrc, const int* __restrict__ edst,
    const float* __restrict__ b1, const float* __restrict__ b2,
    const float* __restrict__ b3,
    const float* __restrict__ lng, const float* __restrict__ lnb,
    const float* __restrict__ bg1, const float* __restrict__ Wg2,
    const float* __restrict__ bg2)
{
    extern __shared__ char sm[];
    const int tid = threadIdx.x, warp = tid >> 5, lane = tid & 31;
    const int e0 = blockIdx.x * 128;

    float* fGate = (float*)(sm + EOFF_GATE);
    int*   iDst  = (int*)(sm + EOFF_DST);
    float* fSS   = (float*)(sm + EOFF_SS);   // [2][128]
    float* fSQ   = (float*)(sm + EOFF_SQ);   // [2][128]

    // ---- gather + h1 + gate (each warp: 8 edges, full width) ----
    {
        float4 b1v = ld4(b1 + lane * 4);
        float4 bgv = ld4(bg1 + lane * 4);
        float4 wgv = ld4(Wg2 + lane * 4);
#pragma unroll 1
        for (int i = 0; i < 8; i++) {
            int r = warp * 8 + i;
            int sidx = esrc[e0 + r];
            int didx = edst[e0 + r];
            const float* us = g_Us + (size_t)sidx * 256;
            const float* ud = g_Ud + (size_t)didx * 256;
            float4 a = ld4(us + lane * 4);
            float4 bq = ld4(ud + lane * 4);
            float h0 = gelu_exact(a.x + bq.x + b1v.x);
            float h1 = gelu_exact(a.y + bq.y + b1v.y);
            float h2 = gelu_exact(a.z + bq.z + b1v.z);
            float h3 = gelu_exact(a.w + bq.w + b1v.w);
            split_store4(sm, r, lane * 4, h0, h1, h2, h3);
            float4 a2 = ld4(us + 128 + lane * 4);
            float4 c2 = ld4(ud + 128 + lane * 4);
            float sg = gelu_exact(a2.x + c2.x + bgv.x) * wgv.x
                     + gelu_exact(a2.y + c2.y + bgv.y) * wgv.y
                     + gelu_exact(a2.z + c2.z + bgv.z) * wgv.z
                     + gelu_exact(a2.w + c2.w + bgv.w) * wgv.w;
#pragma unroll
            for (int off = 1; off < 32; off <<= 1)
                sg += __shfl_xor_sync(0xffffffffu, sg, off);
            if (lane == 0) { fGate[r] = sg; iDst[r] = didx; }
        }
    }
    copy_b_tiles(sm, 4, 5, tid, 512);
    __syncthreads();

    const int wn = warp >> 3, wr = warp & 7;
    const int m0 = wr * 16, n0 = wn * 4;
    float* stage = (float*)(sm + STAGE + warp * STG_WB);
    const int srow = lane >> 1, shalf = lane & 1;
    const int rowc = m0 + srow;
    FragC c[4];

    // ---- MMA1: D1 = h1 @ W2 (this warp's quarter) ----
    warp_gemm3<4>(sm, B_HI0, B_LO0, m0, n0, c);
    __syncthreads();   // all MMA1 reads of A done before overwrite

    // ---- epilogue1: h2 = gelu(D1 + b2) -> A tile ----
#pragma unroll 1
    for (int j = 0; j < 4; j++) {
        wmma::store_matrix_sync(stage, c[j], STG_LD, wmma::mem_row_major);
        __syncwarp();
        const float* sp = stage + srow * STG_LD + shalf * 8;
        int cb = (n0 + j) * 16 + shalf * 8;
        float4 f0 = ld4(b2 + cb), f1 = ld4(b2 + cb + 4);
        split_store4(sm, rowc, cb,
                     gelu_exact(sp[0] + f0.x), gelu_exact(sp[1] + f0.y),
                     gelu_exact(sp[2] + f0.z), gelu_exact(sp[3] + f0.w));
        split_store4(sm, rowc, cb + 4,
                     gelu_exact(sp[4] + f1.x), gelu_exact(sp[5] + f1.y),
                     gelu_exact(sp[6] + f1.z), gelu_exact(sp[7] + f1.w));
        __syncwarp();
    }
    __syncthreads();   // h2 complete before MMA2

    // ---- MMA2: D2 = h2 @ W3 ----
    warp_gemm3<4>(sm, B_HI1, B_LO1, m0, n0, c);

    // ---- LN pass 1: partial sums over this warp's 64 cols ----
    float s = 0.f, ss = 0.f;
#pragma unroll 1
    for (int j = 0; j < 4; j++) {
        wmma::store_matrix_sync(stage, c[j], STG_LD, wmma::mem_row_major);
        __syncwarp();
        const float* sp = stage + srow * STG_LD + shalf * 8;
        int cb = (n0 + j) * 16 + shalf * 8;
        float4 f0 = ld4(b3 + cb), f1 = ld4(b3 + cb + 4);
        float x0 = sp[0] + f0.x, x1 = sp[1] + f0.y, x2 = sp[2] + f0.z, x3 = sp[3] + f0.w;
        float x4 = sp[4] + f1.x, x5 = sp[5] + f1.y, x6 = sp[6] + f1.z, x7 = sp[7] + f1.w;
        s  += x0 + x1 + x2 + x3 + x4 + x5 + x6 + x7;
        ss += x0*x0 + x1*x1 + x2*x2 + x3*x3 + x4*x4 + x5*x5 + x6*x6 + x7*x7;
        __syncwarp();
    }
    s  += __shfl_xor_sync(0xffffffffu, s, 1);
    ss += __shfl_xor_sync(0xffffffffu, ss, 1);
    if (shalf == 0) { fSS[wn * 128 + rowc] = s; fSQ[wn * 128 + rowc] = ss; }
    __syncthreads();

    // ---- LN pass 2: scatter ----
    {
        float st = fSS[rowc] + fSS[128 + rowc];
        float qt = fSQ[rowc] + fSQ[128 + rowc];
        float m = st * 0.0078125f;
        float var = qt * 0.0078125f - m * m;
        float rstd = rsqrtf(var + 1e-5f);
        float gv = 1.0f / (1.0f + expf(-(fGate[rowc] + bg2[0])));
        float* up = g_upd + (size_t)iDst[rowc] * 128;
#pragma unroll 1
        for (int j = 0; j < 4; j++) {
            wmma::store_matrix_sync(stage, c[j], STG_LD, wmma::mem_row_major);
            __syncwarp();
            const float* sp = stage + srow * STG_LD + shalf * 8;
            int cb = (n0 + j) * 16 + shalf * 8;
            float4 f0 = ld4(b3 + cb), f1 = ld4(b3 + cb + 4);
            float4 g0 = ld4(lng + cb), g1 = ld4(lng + cb + 4);
            float4 e0v = ld4(lnb + cb), e1v = ld4(lnb + cb + 4);
            atomicAdd(up + cb + 0, ((sp[0] + f0.x - m) * rstd * g0.x + e0v.x) * gv);
            atomicAdd(up + cb + 1, ((sp[1] + f0.y - m) * rstd * g0.y + e0v.y) * gv);
            atomicAdd(up + cb + 2, ((sp[2] + f0.z - m) * rstd * g0.z + e0v.z) * gv);
            atomicAdd(up + cb + 3, ((sp[3] + f0.w - m) * rstd * g0.w + e0v.w) * gv);
            atomicAdd(up + cb + 4, ((sp[4] + f1.x - m) * rstd * g1.x + e1v.x) * gv);
            atomicAdd(up + cb + 5, ((sp[5] + f1.y - m) * rstd * g1.y + e1v.y) * gv);
            atomicAdd(up + cb + 6, ((sp[6] + f1.z - m) * rstd * g1.z + e1v.z) * gv);
            atomicAdd(up + cb + 7, ((sp[7] + f1.w - m) * rstd * g1.w + e1v.w) * gv);
            __syncwarp();
        }
    }
}

// =============================== out kernel (SIMT) ===============================
__global__ __launch_bounds__(256, 2) void out_kernel(
    const float* __restrict__ Wout, const float* __restrict__ bout,
    float* __restrict__ out)
{
    __shared__ float sU[64 * 128];
    __shared__ float sW[1024];
    const int tid = threadIdx.x, warp = tid >> 5, lane = tid & 31;
    const int ty = tid >> 4, tx = tid & 15;
    const size_t row0 = (size_t)blockIdx.x * 64;

#pragma unroll
    for (int i = 0; i < 8; i++) {
        int r = warp + i * 8;
        size_t gr = row0 + r;
        float4 v = make_float4(0.f, 0.f, 0.f, 0.f);
        if (gr < NN) v = ld4(g_upd + gr * 128 + lane * 4);
        st4(sU + r * 128 + lane * 4, v);
    }
    u64 acc[4][4];
    ZERO_ACC2(acc);
    gemm64p(sU, Wout, sW, acc, tid);

    float4 b0 = ld4(bout + tx * 4), b1v = ld4(bout + 64 + tx * 4);
#pragma unroll
    for (int r = 0; r < 4; r++) {
        size_t gr = row0 + ty * 4 + r;
        if (gr < NN) {
            float x[8]; UNPACK8(x, acc[r]);
            st4(out + gr * 128 + tx * 4,
                make_float4(x[0] + b0.x, x[1] + b0.y, x[2] + b0.z, x[3] + b0.w));
            st4(out + gr * 128 + 64 + tx * 4,
                make_float4(x[4] + b1v.x, x[5] + b1v.y, x[6] + b1v.z, x[7] + b1v.w));
        }
    }
}

extern "C" void kernel_launch(void* const* d_in, const int* in_sizes, int n_in,
                              void* d_out, int out_size)
{
    const float* feat  = (const float*)d_in[0];
    const int*   esrc  = (const int*)d_in[1];
    const int*   edst  = (const int*)d_in[2];
    const float* W_src = (const float*)d_in[3];
    const float* b_src = (const float*)d_in[4];
    const float* W_dst = (const float*)d_in[5];
    const float* b_dst = (const float*)d_in[6];
    const float* W1a   = (const float*)d_in[7];
    const float* W1b   = (const float*)d_in[8];
    const float* b1    = (const float*)d_in[9];
    const float* W2    = (const float*)d_in[10];
    const float* b2    = (const float*)d_in[11];
    const float* W3    = (const float*)d_in[12];
    const float* b3    = (const float*)d_in[13];
    const float* ln_g  = (const float*)d_in[14];
    const float* ln_b  = (const float*)d_in[15];
    const float* Wg1a  = (const float*)d_in[16];
    const float* Wg1b  = (const float*)d_in[17];
    const float* bg1   = (const float*)d_in[18];
    const float* Wg2   = (const float*)d_in[19];
    const float* bg2   = (const float*)d_in[20];
    const float* W_out = (const float*)d_in[21];
    const float* b_out = (const float*)d_in[22];
    float* out = (float*)d_out;

    cudaFuncSetAttribute(node_kernel, cudaFuncAttributeMaxDynamicSharedMemorySize, NODE_SMEM);
    cudaFuncSetAttribute(edge_kernel, cudaFuncAttributeMaxDynamicSharedMemorySize, EDGE_SMEM);

    compose_kernel<<<8, 256>>>(W_src, W_dst, W1a, Wg1a, W1b, Wg1b);
    bias_kernel<<<4, 128>>>(b_src, b_dst, W1a, Wg1a, W1b, Wg1b);
    split_kernel<<<6, 256>>>(W2, W3);
    zero_upd_kernel<<<(NN * 128 / 4 + 255) / 256, 256>>>();
    node_kernel<<<2 * 782, 512, NODE_SMEM>>>(feat);
    edge_kernel<<<EE / 128, 512, EDGE_SMEM>>>(esrc, edst, b1, b2, b3,
                                              ln_g, ln_b, bg1, Wg2, bg2);
    out_kernel<<<(NN + 63) / 64, 256>>>(W_out, b_out, out);
}